// round 11
// baseline (speedup 1.0000x reference)
#include <cuda_runtime.h>
#include <cuda_bf16.h>
#include <math.h>

#define TSEQ 2048
#define BB 8
#define DH 64
#define DM 1024
#define NTOK (BB*TSEQ)
#define CCH 16
#define NCH (TSEQ/CCH)   /* 128 */
#define NST 896
#define KPAD 68
#define NT 512
#define NW 192
#define NGRP 32
#define PSTR 97

// scratch (device globals -- no allocation allowed)
__device__ float g_q[NTOK*DH];
__device__ float g_k[NTOK*DH];
__device__ float g_v[NTOK*DH];
__device__ float g_prefix[BB*NCH*NST];
__device__ float g_gtot[BB*NGRP*NST];
__device__ float g_goff[BB*NGRP*NST];
__device__ __nv_bfloat16 g_wh[DM*NW];
__device__ __nv_bfloat16 g_wl[DM*NW];
__device__ __nv_bfloat16 g_ah[NTOK*DH];
__device__ __nv_bfloat16 g_al[NTOK*DH];
__device__ __nv_bfloat16 g_woh[DH*DM];
__device__ __nv_bfloat16 g_wol[DH*DM];

struct BasePtrs { const float* p[16]; };

// ---------------- helpers ----------------
__device__ __forceinline__ void cp_async16(void* sptr, const void* gptr){
    unsigned s = (unsigned)__cvta_generic_to_shared(sptr);
    asm volatile("cp.async.ca.shared.global [%0], [%1], 16;" :: "r"(s), "l"(gptr));
}
__device__ __forceinline__ float dot4v(float4 a, float4 b){
    return fmaf(a.x,b.x, fmaf(a.y,b.y, fmaf(a.z,b.z, a.w*b.w)));
}
__device__ __forceinline__ void fma4(float4 &acc, float s, float4 v){
    acc.x = fmaf(s, v.x, acc.x); acc.y = fmaf(s, v.y, acc.y);
    acc.z = fmaf(s, v.z, acc.z); acc.w = fmaf(s, v.w, acc.w);
}
__device__ __forceinline__ unsigned smem_u32(const void* p){
    return (unsigned)__cvta_generic_to_shared(p);
}
__device__ __forceinline__ void ldmx4(unsigned &r0, unsigned &r1, unsigned &r2, unsigned &r3, const void* p){
    asm volatile("ldmatrix.sync.aligned.m8n8.x4.shared.b16 {%0,%1,%2,%3}, [%4];"
        : "=r"(r0),"=r"(r1),"=r"(r2),"=r"(r3) : "r"(smem_u32(p)));
}
__device__ __forceinline__ void ldmx4t(unsigned &r0, unsigned &r1, unsigned &r2, unsigned &r3, const void* p){
    asm volatile("ldmatrix.sync.aligned.m8n8.x4.trans.shared.b16 {%0,%1,%2,%3}, [%4];"
        : "=r"(r0),"=r"(r1),"=r"(r2),"=r"(r3) : "r"(smem_u32(p)));
}
__device__ __forceinline__ void mma16816(float* c, unsigned a0,unsigned a1,unsigned a2,unsigned a3,
                                         unsigned b0, unsigned b1){
    asm volatile("mma.sync.aligned.m16n8k16.row.col.f32.bf16.bf16.f32 "
        "{%0,%1,%2,%3}, {%4,%5,%6,%7}, {%8,%9}, {%0,%1,%2,%3};"
        : "+f"(c[0]),"+f"(c[1]),"+f"(c[2]),"+f"(c[3])
        : "r"(a0),"r"(a1),"r"(a2),"r"(a3),"r"(b0),"r"(b1));
}

__device__ __forceinline__ int Knro(int l){ return (l==0)?0:(l==1)?32:(l==2)?64:80; }
__device__ __forceinline__ int Kwso(int l){ return (l==0)?0:(l==1)?128:(l==2)?384:512; }
__device__ __forceinline__ int Kbso(int l){ return (l==0)?0:(l==1)?16:(l==2)?80:208; }
__device__ __forceinline__ int Knoff(int l){ return (l==0)?0:(l==1)?8:(l==2)?12:14; }

// ---------------- weight split prep ----------------
__global__ __launch_bounds__(256) void wprep_kernel(const float* __restrict__ Wq,
                                                    const float* __restrict__ Wk,
                                                    const float* __restrict__ Wv,
                                                    const float* __restrict__ Wo){
    int idx = blockIdx.x*256 + threadIdx.x;
    if (idx < DM*NW){
        int k = idx / NW, n = idx - k*NW;
        const float* W = (n<64)?Wq:(n<128?Wk:Wv);
        float w = W[(size_t)k*DH + (n&63)];
        __nv_bfloat16 hi = __float2bfloat16(w);
        g_wh[idx] = hi;
        g_wl[idx] = __float2bfloat16(w - __bfloat162float(hi));
    } else {
        int j = idx - DM*NW;
        float w = Wo[j];
        __nv_bfloat16 hi = __float2bfloat16(w);
        g_woh[j] = hi;
        g_wol[j] = __float2bfloat16(w - __bfloat162float(hi));
    }
}

// ---------------- QKV via mma.sync bf16x3, BM=128 (LSU-amortized) ----------------
#define ASTR 24
#define BSTR 200
#define ABUF (128*ASTR)
#define BBUF (16*BSTR)
#define QKV_BYTES ((2*ABUF*2 + 2*BBUF*2)*2)
__global__ __launch_bounds__(256) void qkv_mma_kernel(const float* __restrict__ x){
    extern __shared__ __nv_bfloat16 qs[];
    __nv_bfloat16* sAh = qs;                    // [2][128*ASTR]
    __nv_bfloat16* sAl = sAh + 2*ABUF;
    __nv_bfloat16* sBh = sAl + 2*ABUF;          // [2][16*BSTR]
    __nv_bfloat16* sBl = sBh + 2*BBUF;

    const int tid = threadIdx.x;
    const int wid = tid >> 5, lane = tid & 31;
    const int wy = wid & 3, wx = wid >> 2;
    const int rb = blockIdx.x * 128;
    const int arow = tid >> 1, ac8 = (tid & 1)*8;   // 8 floats per thread per stage

    float acc[2][12][4];
#pragma unroll
    for (int m=0;m<2;m++)
#pragma unroll
        for (int i=0;i<12;i++){ acc[m][i][0]=acc[m][i][1]=acc[m][i][2]=acc[m][i][3]=0.f; }

    auto loadB = [&](int k0, int buf){
#pragma unroll
        for (int i=0;i<3;i++){
            int idx = tid + i*256;
            int m2 = (idx >= 384);
            int id2 = idx - m2*384;
            int r = id2 / 24, c8 = id2 - r*24;
            const __nv_bfloat16* src = (m2 ? g_wl : g_wh) + (size_t)(k0+r)*NW + c8*8;
            __nv_bfloat16* dst = (m2 ? sBl : sBh) + buf*BBUF + r*BSTR + c8*8;
            cp_async16(dst, src);
        }
    };
    auto storeA = [&](float4 v0, float4 v1, int buf){
        __nv_bfloat16 h[8]; float lo[8];
        float vv[8] = {v0.x,v0.y,v0.z,v0.w, v1.x,v1.y,v1.z,v1.w};
#pragma unroll
        for (int i=0;i<8;i++){ h[i]=__float2bfloat16(vv[i]); lo[i]=vv[i]-__bfloat162float(h[i]); }
        __nv_bfloat162 hh0=__halves2bfloat162(h[0],h[1]), hh1=__halves2bfloat162(h[2],h[3]);
        __nv_bfloat162 hh2=__halves2bfloat162(h[4],h[5]), hh3=__halves2bfloat162(h[6],h[7]);
        __nv_bfloat162 ll0=__floats2bfloat162_rn(lo[0],lo[1]), ll1=__floats2bfloat162_rn(lo[2],lo[3]);
        __nv_bfloat162 ll2=__floats2bfloat162_rn(lo[4],lo[5]), ll3=__floats2bfloat162_rn(lo[6],lo[7]);
        __nv_bfloat16* dh = sAh + buf*ABUF + arow*ASTR + ac8;
        __nv_bfloat16* dl = sAl + buf*ABUF + arow*ASTR + ac8;
        *(uint2*)dh     = make_uint2(*(unsigned*)&hh0, *(unsigned*)&hh1);
        *(uint2*)(dh+4) = make_uint2(*(unsigned*)&hh2, *(unsigned*)&hh3);
        *(uint2*)dl     = make_uint2(*(unsigned*)&ll0, *(unsigned*)&ll1);
        *(uint2*)(dl+4) = make_uint2(*(unsigned*)&ll2, *(unsigned*)&ll3);
    };

    const float* xrow = x + (size_t)(rb+arow)*DM + ac8;
    float4 av0 = *(const float4*)xrow;
    float4 av1 = *(const float4*)(xrow+4);
    loadB(0, 0);
    asm volatile("cp.async.commit_group;\n");
    storeA(av0, av1, 0);
    asm volatile("cp.async.wait_group 0;\n");
    __syncthreads();
    av0 = *(const float4*)(xrow + 16);
    av1 = *(const float4*)(xrow + 20);

    const int a_off0 = (wy*32 + (lane&15))*ASTR + (lane>>4)*8;
    const int b_off  = (lane&15)*BSTR + wx*96 + (lane>>4)*8;

    for(int kt=0; kt<64; kt++){
        const int buf = kt & 1;
        if (kt < 63){
            loadB((kt+1)*16, buf^1);
            asm volatile("cp.async.commit_group;\n");
            storeA(av0, av1, buf^1);
            if (kt < 62){
                av0 = *(const float4*)(xrow + (kt+2)*16);
                av1 = *(const float4*)(xrow + (kt+2)*16 + 4);
            }
        }
        unsigned ah[2][4], al[2][4];
#pragma unroll
        for (int mt=0;mt<2;mt++){
            ldmx4(ah[mt][0],ah[mt][1],ah[mt][2],ah[mt][3], sAh + buf*ABUF + a_off0 + mt*16*ASTR);
            ldmx4(al[mt][0],al[mt][1],al[mt][2],al[mt][3], sAl + buf*ABUF + a_off0 + mt*16*ASTR);
        }
#pragma unroll
        for(int nb=0; nb<6; nb++){
            unsigned bh0,bh1,bh2,bh3, bl0,bl1,bl2,bl3;
            ldmx4t(bh0,bh1,bh2,bh3, sBh + buf*BBUF + b_off + nb*16);
            ldmx4t(bl0,bl1,bl2,bl3, sBl + buf*BBUF + b_off + nb*16);
#pragma unroll
            for (int mt=0;mt<2;mt++){
                mma16816(acc[mt][2*nb],   ah[mt][0],ah[mt][1],ah[mt][2],ah[mt][3], bh0,bh1);
                mma16816(acc[mt][2*nb],   ah[mt][0],ah[mt][1],ah[mt][2],ah[mt][3], bl0,bl1);
                mma16816(acc[mt][2*nb],   al[mt][0],al[mt][1],al[mt][2],al[mt][3], bh0,bh1);
                mma16816(acc[mt][2*nb+1], ah[mt][0],ah[mt][1],ah[mt][2],ah[mt][3], bh2,bh3);
                mma16816(acc[mt][2*nb+1], ah[mt][0],ah[mt][1],ah[mt][2],ah[mt][3], bl2,bl3);
                mma16816(acc[mt][2*nb+1], al[mt][0],al[mt][1],al[mt][2],al[mt][3], bh2,bh3);
            }
        }
        if (kt < 63){
            asm volatile("cp.async.wait_group 0;\n");
        }
        __syncthreads();
    }

#pragma unroll
    for (int mt=0;mt<2;mt++){
        const int row0 = rb + wy*32 + mt*16 + (lane>>2);
#pragma unroll
        for (int t=0; t<12; t++){
            int col = wx*96 + t*8 + (lane&3)*2;
            bool act = (col < 128);
            float* base = (col < 64) ? g_q : (col < 128 ? g_k : g_v);
            int cc = col & 63;
            float v0 = acc[mt][t][0], v1 = acc[mt][t][1], v2 = acc[mt][t][2], v3 = acc[mt][t][3];
            if (act){
                v0 = (v0>0.f)? v0+1.f : expf(v0);
                v1 = (v1>0.f)? v1+1.f : expf(v1);
                v2 = (v2>0.f)? v2+1.f : expf(v2);
                v3 = (v3>0.f)? v3+1.f : expf(v3);
            }
            base[(size_t)row0*DH + cc]       = v0;
            base[(size_t)row0*DH + cc + 1]   = v1;
            base[(size_t)(row0+8)*DH + cc]   = v2;
            base[(size_t)(row0+8)*DH + cc+1] = v3;
        }
    }
}

// =====================================================================
// shared LUT builders
// =====================================================================
__device__ __forceinline__ void build_node_lut(int* s_nd, int tid){
    if (tid < 15){
        int l = (tid<8)?0:(tid<12)?1:(tid<14)?2:3;
        int n = tid - Knoff(l);
        int bs = 4<<l, r = (l==0)?4:8;
        s_nd[tid*5+0]=bs; s_nd[tid*5+1]=r; s_nd[tid*5+2]=Knro(l)+n*r;
        s_nd[tid*5+3]=2*bs*n; s_nd[tid*5+4]=Kbso(l);
    }
}
__device__ __forceinline__ void build_ws_lut(int* s_lutAB, int tid, int nthr){
    for (int m = tid; m < 576; m += nthr){
        int l = (m<128)?0:(m<384)?1:(m<512)?2:3;
        int r = (l==0)?4:8;
        int rem = m - Kwso(l);
        int rr2 = r*r;
        int n = rem / rr2;
        int ij = rem - n*rr2;
        int i = ij / r, j = ij - i*r;
        int pb = Knro(l) + n*r;
        s_lutAB[m] = (pb+i) | ((pb+j)<<16);
    }
}
__device__ __forceinline__ void build_chunk_lut(int* s_ck, int tid){
    if (tid < 20){
        int c = tid, m, dd0=0, ext=0, ec=0;
        if (c < 13){ m = c; }
        else if (c == 13){ m=12; dd0=8; ext=1; ec=0; }
        else if (c == 14){ m=13; }
        else if (c == 15){ m=13; dd0=8; ext=1; ec=1; }
        else if (c == 16){ m=14; }
        else { m=14; dd0=8*(c-16); ext=1; ec=c-15; }
        s_ck[c] = m | (dd0<<8) | (ext<<16) | (ec<<20);
    }
}

// =====================================================================
// Pass 1: per-group (4 chunks) sums; prj transposed [16][PSTR]
// =====================================================================
#define P1_FLOATS (2176 + 2*16*PSTR + 928 + 1280)
#define P1_BYTES (P1_FLOATS*4 + (75+576+20)*4)
__global__ __launch_bounds__(512,2) void chunk_sum4_kernel(BasePtrs bp){
    extern __shared__ float sm[];
    float* s_k    = sm;
    float* s_v    = s_k + 16*KPAD;
    float* prjULT = s_v + 16*KPAD;
    float* prjVRT = prjULT + 16*PSTR;
    float* sUL    = prjVRT + 16*PSTR;
    float* sVR    = sUL + 464;
    float* extP   = sVR + 464;
    int*   s_nd   = (int*)(extP + 1280);
    int*   lutAB  = s_nd + 75;
    int*   s_ck   = lutAB + 576;

    const int tid = threadIdx.x;
    const int blk = blockIdx.x;
    const int b = blk / NGRP, grp = blk % NGRP;

    for (int i=tid;i<464;i+=NT){
        int l = (i<16)?0:(i<80)?1:(i<208)?2:3;
        int off = i - Kbso(l);
        sUL[i] = bp.p[l][off];
        sVR[i] = bp.p[4+l][off];
    }
    build_node_lut(s_nd, tid);
    build_ws_lut(lutAB, tid, NT);
    build_chunk_lut(s_ck, tid);
    __syncthreads();

    float sreg[2][4];

    for (int j=0;j<4;j++){
        const int c = grp*4 + j;
        const float* gk = g_k + ((size_t)b*TSEQ + c*CCH)*DH;
        const float* gv = g_v + ((size_t)b*TSEQ + c*CCH)*DH;
        if (tid < 512){
            int arr = tid>>8;
            int rem = tid & 255; int row = rem>>4, g = rem&15;
            const float* src = (arr==0?gk:gv) + row*64 + g*4;
            float* dst = (arr==0?s_k:s_v) + row*KPAD + g*4;
            *(float4*)dst = *(const float4*)src;
        }
        __syncthreads();

        if (tid < 320){
            int cd = s_ck[tid>>4]; int s = tid&15;
            int m = cd & 31, dd0 = (cd>>8)&63, isext=(cd>>16)&1, ec=(cd>>20)&7;
            int bs=s_nd[m*5], r=s_nd[m*5+1], pb=s_nd[m*5+2], topo=s_nd[m*5+3], bso=s_nd[m*5+4];
            const float* kt = s_k + s*KPAD + topo + dd0;
            const float* vb = s_v + s*KPAD + topo + bs + dd0;
            const float* Ub = sUL + bso + dd0*r;
            const float* Wb = sVR + bso + dd0*r;
            if (r == 4){
                float4 aU=make_float4(0,0,0,0), aV=aU;
#pragma unroll
                for (int d=0; d<4; d++){
                    float kd=kt[d], vd=vb[d];
                    float4 u=*(const float4*)(Ub+d*4), w=*(const float4*)(Wb+d*4);
                    fma4(aU,kd,u); fma4(aV,vd,w);
                }
                float au[4]={aU.x,aU.y,aU.z,aU.w}, avv[4]={aV.x,aV.y,aV.z,aV.w};
#pragma unroll
                for (int i=0;i<4;i++){
                    prjULT[s*PSTR + pb+i]=au[i];
                    prjVRT[s*PSTR + pb+i]=avv[i];
                }
            } else {
                float aU[8], aV[8];
#pragma unroll
                for (int i=0;i<8;i++){ aU[i]=0.f; aV[i]=0.f; }
#pragma unroll
                for (int d=0; d<8; d++){
                    float kd=kt[d], vd=vb[d];
                    float4 u0=*(const float4*)(Ub+d*8), u1=*(const float4*)(Ub+d*8+4);
                    float4 w0=*(const float4*)(Wb+d*8), w1=*(const float4*)(Wb+d*8+4);
                    aU[0]=fmaf(kd,u0.x,aU[0]); aU[1]=fmaf(kd,u0.y,aU[1]); aU[2]=fmaf(kd,u0.z,aU[2]); aU[3]=fmaf(kd,u0.w,aU[3]);
                    aU[4]=fmaf(kd,u1.x,aU[4]); aU[5]=fmaf(kd,u1.y,aU[5]); aU[6]=fmaf(kd,u1.z,aU[6]); aU[7]=fmaf(kd,u1.w,aU[7]);
                    aV[0]=fmaf(vd,w0.x,aV[0]); aV[1]=fmaf(vd,w0.y,aV[1]); aV[2]=fmaf(vd,w0.z,aV[2]); aV[3]=fmaf(vd,w0.w,aV[3]);
                    aV[4]=fmaf(vd,w1.x,aV[4]); aV[5]=fmaf(vd,w1.y,aV[5]); aV[6]=fmaf(vd,w1.z,aV[6]); aV[7]=fmaf(vd,w1.w,aV[7]);
                }
                if (!isext){
#pragma unroll
                    for (int i=0;i<8;i++){
                        prjULT[s*PSTR + pb+i]=aU[i];
                        prjVRT[s*PSTR + pb+i]=aV[i];
                    }
                } else {
#pragma unroll
                    for (int i=0;i<8;i++){
                        extP[((0*5+ec)*8+i)*16+s]=aU[i];
                        extP[((1*5+ec)*8+i)*16+s]=aV[i];
                    }
                }
            }
        }
        __syncthreads();
        if (tid < 256){
            int a=tid>>7, i=(tid>>4)&7, s=tid&15;
            float* base = prjULT + a*(16*PSTR);
            base[s*PSTR + 64+i] += extP[((a*5+0)*8+i)*16+s];
            base[s*PSTR + 72+i] += extP[((a*5+1)*8+i)*16+s];
            base[s*PSTR + 80+i] += extP[((a*5+2)*8+i)*16+s] + extP[((a*5+3)*8+i)*16+s] + extP[((a*5+4)*8+i)*16+s];
        }
        __syncthreads();

#pragma unroll
        for (int o=0;o<2;o++){
            int e = tid + o*512;
            if (e < NST){
                float acc = 0.f;
                if (e < 256){
                    int n=e>>4, i=(e>>2)&3, j2=e&3;
                    int ki=4*n+i, vi=4*n+j2;
#pragma unroll
                    for (int s=0;s<CCH;s++) acc = fmaf(s_k[s*KPAD+ki], s_v[s*KPAD+vi], acc);
                } else if (e < 832){
                    int m = e-256;
                    int ab = lutAB[m]; int a = ab & 0xffff, b3 = ab >> 16;
#pragma unroll
                    for (int s=0;s<16;s++)
                        acc = fmaf(prjULT[s*PSTR+a], prjVRT[s*PSTR+b3], acc);
                } else {
                    int d = e-832;
#pragma unroll
                    for (int s=0;s<CCH;s++) acc += s_k[s*KPAD+d];
                }
                sreg[o][j] = acc;
            }
        }
        __syncthreads();
    }

#pragma unroll
    for (int o=0;o<2;o++){
        int e = tid + o*512;
        if (e < NST){
            float run = 0.f;
#pragma unroll
            for (int j=0;j<4;j++){
                g_prefix[(size_t)(blk*4+j)*NST + e] = run;
                run += sreg[o][j];
            }
            g_gtot[(size_t)blk*NST + e] = run;
        }
    }
}

// =====================================================================
// Pass 2: exclusive prefix over 32 group totals per batch (MLP=32)
// =====================================================================
__global__ __launch_bounds__(128) void midscan_kernel(){
    const int b = blockIdx.y;
    const int e = blockIdx.x*128 + threadIdx.x;
    const float* gt = g_gtot + (size_t)b*NGRP*NST + e;
    float*       go = g_goff + (size_t)b*NGRP*NST + e;
    float v[NGRP];
#pragma unroll
    for (int j=0;j<NGRP;j++) v[j] = gt[(size_t)j*NST];
    float run = 0.f;
#pragma unroll
    for (int j=0;j<NGRP;j++){ go[(size_t)j*NST] = run; run += v[j]; }
}

// =====================================================================
// Pass 3: fully parallel intra-chunk attention (unchanged from R10)
// =====================================================================
#define P3_FLOATS (3264 + 5632 + 1856 + 896 + 3840 + 3840 + 2560 + 256 + 16 + 1496 + 1496 + 1088)
#define P3_BYTES (P3_FLOATS*4 + (75 + 88*3 + 20)*4)
__global__ __launch_bounds__(512,2) void chunk_scan_kernel(BasePtrs bp){
    extern __shared__ float sm[];
    float* s_k    = sm;
    float* s_v    = s_k + 16*KPAD;
    float* s_q    = s_v + 16*KPAD;
    float* prjULT = s_q + 16*KPAD;
    float* prjVRT = prjULT + 1408;
    float* prjXT  = prjVRT + 1408;
    float* prjLT  = prjXT + 1408;
    float* sUL    = prjLT + 1408;
    float* sVR    = sUL + 464;
    float* sUR    = sVR + 464;
    float* sVL    = sUR + 464;
    float* s_leaf = sVL + 464;
    float* s_Ws   = s_leaf + 256;
    float* s_z    = s_Ws + 576;
    float* Asc    = s_z + 64;
    float* Bsc    = Asc + 3840;
    float* extP   = Bsc + 3840;
    float* Dsc    = extP + 2560;
    float* s_den  = Dsc + 256;
    float* TT     = s_den + 16;
    float* TBB    = TT + 1496;
    float* yl     = TBB + 1496;
    int*   s_nd   = (int*)(yl + 1088);
    int*   lutP   = s_nd + 75;
    int*   lutWT  = lutP + 88;
    int*   lutWB  = lutWT + 88;
    int*   s_ck   = lutWB + 88;

    const int tid = threadIdx.x;
    const int blk = blockIdx.x;
    const int b = blk / (NCH/2), cp = blk % (NCH/2);

    for (int i=tid;i<464;i+=NT){
        int l = (i<16)?0:(i<80)?1:(i<208)?2:3;
        int off = i - Kbso(l);
        sUL[i] = bp.p[l   ][off];
        sVR[i] = bp.p[4+l ][off];
        sUR[i] = bp.p[8+l ][off];
        sVL[i] = bp.p[12+l][off];
    }
    build_node_lut(s_nd, tid);
    build_chunk_lut(s_ck, tid);
    if (tid < 88){
        int i88 = tid;
        int l = (i88<32)?0:(i88<64)?1:(i88<80)?2:3;
        int r = (l==0)?4:8;
        int rem = i88 - Knro(l);
        int n = rem / r, i = rem - n*r;
        int pb = Knro(l) + n*r;
        int ng = Knoff(l) + n;
        lutP[i88]  = pb | (ng<<8) | (r<<16);
        lutWT[i88] = Kwso(l) + n*r*r + i*r;
        lutWB[i88] = Kwso(l) + n*r*r + i;
    }

    for (int cc=0; cc<2; cc++){
        const int c = cp*2 + cc;
        const int ci = b*NCH + c;
        const float* gk = g_k + ((size_t)b*TSEQ + c*CCH)*DH;
        const float* gv = g_v + ((size_t)b*TSEQ + c*CCH)*DH;
        const float* gq = g_q + ((size_t)b*TSEQ + c*CCH)*DH;
        __nv_bfloat16* g_oh = g_ah + ((size_t)b*TSEQ + c*CCH)*DH;
        __nv_bfloat16* g_ol = g_al + ((size_t)b*TSEQ + c*CCH)*DH;

        for (int i=tid;i<768;i+=NT){
            int arr = i>>8;
            int rem = i & 255; int row = rem>>4, g = rem&15;
            const float* src = (arr==0?gk:(arr==1?gv:gq)) + row*64 + g*4;
            float* dst = (arr==0?s_k:(arr==1?s_v:s_q)) + row*KPAD + g*4;
            *(float4*)dst = *(const float4*)src;
        }
        {
            const float* gp = g_prefix + (size_t)ci*NST;
            const float* gof = g_goff + ((size_t)(b*NGRP) + (c>>2))*NST;
            for (int e=tid;e<NST;e+=NT){
                float vle = gp[e] + gof[e];
                if (e<256) s_leaf[e]=vle;
                else if (e<832) s_Ws[e-256]=vle;
                else s_z[e-832]=vle;
            }
        }
        __syncthreads();

        if (tid < 320){
            int cd = s_ck[tid>>4]; int s = tid&15;
            int m = cd & 31, dd0 = (cd>>8)&63, isext=(cd>>16)&1, ec=(cd>>20)&7;
            int bs=s_nd[m*5], r=s_nd[m*5+1], pb=s_nd[m*5+2], topo=s_nd[m*5+3], bso=s_nd[m*5+4];
            const float* kt = s_k + s*KPAD + topo + dd0;
            const float* vb = s_v + s*KPAD + topo + bs + dd0;
            const float* qt = s_q + s*KPAD + topo + dd0;
            const float* qb = s_q + s*KPAD + topo + bs + dd0;
            const float* Ub = sUL + bso + dd0*r;
            const float* Wb = sVR + bso + dd0*r;
            const float* Xb = sVL + bso + dd0*r;
            if (r == 4){
                float4 aU=make_float4(0,0,0,0), aV=aU, aX=aU, aL=aU;
#pragma unroll
                for (int d=0; d<4; d++){
                    float kd=kt[d], vd=vb[d], qtd=qt[d], qbd=qb[d];
                    float4 u=*(const float4*)(Ub+d*4), w=*(const float4*)(Wb+d*4), x=*(const float4*)(Xb+d*4);
                    fma4(aU,kd,u); fma4(aV,vd,w); fma4(aX,qbd,w); fma4(aL,qtd,x);
                }
                float t0[4]={aU.x,aU.y,aU.z,aU.w}, t1[4]={aV.x,aV.y,aV.z,aV.w};
                float t2[4]={aX.x,aX.y,aX.z,aX.w}, t3[4]={aL.x,aL.y,aL.z,aL.w};
#pragma unroll
                for (int i=0;i<4;i++){
                    prjULT[(pb+i)*16+s]=t0[i];
                    prjVRT[(pb+i)*16+s]=t1[i];
                    prjXT [(pb+i)*16+s]=t2[i];
                    prjLT [(pb+i)*16+s]=t3[i];
                }
            } else {
                {
                    float aU[8], aV[8];
#pragma unroll
                    for (int i=0;i<8;i++){ aU[i]=0.f; aV[i]=0.f; }
#pragma unroll
                    for (int d=0; d<8; d++){
                        float kd=kt[d], vd=vb[d];
                        float4 u0=*(const float4*)(Ub+d*8), u1=*(const float4*)(Ub+d*8+4);
                        float4 w0=*(const float4*)(Wb+d*8), w1=*(const float4*)(Wb+d*8+4);
                        aU[0]=fmaf(kd,u0.x,aU[0]); aU[1]=fmaf(kd,u0.y,aU[1]); aU[2]=fmaf(kd,u0.z,aU[2]); aU[3]=fmaf(kd,u0.w,aU[3]);
                        aU[4]=fmaf(kd,u1.x,aU[4]); aU[5]=fmaf(kd,u1.y,aU[5]); aU[6]=fmaf(kd,u1.z,aU[6]); aU[7]=fmaf(kd,u1.w,aU[7]);
                        aV[0]=fmaf(vd,w0.x,aV[0]); aV[1]=fmaf(vd,w0.y,aV[1]); aV[2]=fmaf(vd,w0.z,aV[2]); aV[3]=fmaf(vd,w0.w,aV[3]);
                        aV[4]=fmaf(vd,w1.x,aV[4]); aV[5]=fmaf(vd,w1.y,aV[5]); aV[6]=fmaf(vd,w1.z,aV[6]); aV[7]=fmaf(vd,w1.w,aV[7]);
                    }
                    if (!isext){
#pragma unroll
                        for (int i=0;i<8;i++){ prjULT[(pb+i)*16+s]=aU[i]; prjVRT[(pb+i)*16+s]=aV[i]; }
                    } else {
#pragma unroll
                        for (int i=0;i<8;i++){
                            extP[((0*5+ec)*8+i)*16+s]=aU[i];
                            extP[((1*5+ec)*8+i)*16+s]=aV[i];
                        }
                    }
                }
                {
                    float aX[8], aL[8];
#pragma unroll
                    for (int i=0;i<8;i++){ aX[i]=0.f; aL[i]=0.f; }
#pragma unroll
                    for (int d=0; d<8; d++){
                        float qbd=qb[d], qtd=qt[d];
                        float4 w0=*(const float4*)(Wb+d*8), w1=*(const float4*)(Wb+d*8+4);
                        float4 x0=*(const float4*)(Xb+d*8), x1=*(const float4*)(Xb+d*8+4);
                        aX[0]=fmaf(qbd,w0.x,aX[0]); aX[1]=fmaf(qbd,w0.y,aX[1]); aX[2]=fmaf(qbd,w0.z,aX[2]); aX[3]=fmaf(qbd,w0.w,aX[3]);
                        aX[4]=fmaf(qbd,w1.x,aX[4]); aX[5]=fmaf(qbd,w1.y,aX[5]); aX[6]=fmaf(qbd,w1.z,aX[6]); aX[7]=fmaf(qbd,w1.w,aX[7]);
                        aL[0]=fmaf(qtd,x0.x,aL[0]); aL[1]=fmaf(qtd,x0.y,aL[1]); aL[2]=fmaf(qtd,x0.z,aL[2]); aL[3]=fmaf(qtd,x0.w,aL[3]);
                        aL[4]=fmaf(qtd,x1.x,aL[4]); aL[5]=fmaf(qtd,x1.y,aL[5]); aL[6]=fmaf(qtd,x1.z,aL[6]); aL[7]=fmaf(qtd,x1.w,aL[7]);
                    }
                    if (!isext){
#pragma unroll
                        for (int i=0;i<8;i++){ prjXT[(pb+i)*16+s]=aX[i]; prjLT[(pb+i)*16+s]=aL[i]; }
                    } else {
#pragma unroll
                        for (int i=0;i<8;i++){
                            extP[((2*5+ec)*8+i)*16+s]=aX[i];
                            extP[((3*5+ec)*8+i)*16+s]=aL[i];
                        }
                    }
                }
            }
        } else {
            int j = tid - 320;
#pragma unroll
            for (int rep=0; rep<2; rep++){
                if (j < 256){
                    int t = j>>4, s = j&15;
                    float acc = 0.f;
#pragma unroll
                    for (int g=0;g<16;g++)
                        acc += dot4v(*(const float4*)&s_k[s*KPAD+4*g], *(const float4*)&s_q[t*KPAD+4*g]);
                    Dsc[j] = acc;
                }
                j += 192;
            }
        }
        __syncthreads();
        {
            int a=tid>>7, i=(tid>>4)&7, s=tid&15;
            float* base = prjULT + a*1408;
            base[(64+i)*16+s] += extP[((a*5+0)*8+i)*16+s];
            base[(72+i)*16+s] += extP[((a*5+1)*8+i)*16+s];
            base[(80+i)*16+s] += extP[((a*5+2)*8+i)*16+s] + extP[((a*5+3)*8+i)*16+s] + extP[((a*5+4)*8+i)*16+s];
        }
        __syncthreads();

        for (int j=tid; j<752; j+=NT){
            if (j < 240){
                int ng = j>>4, t = j&15;
                int pb = s_nd[ng*5+2];
                float4 a0=make_float4(0,0,0,0), a1=a0, a2=a0, a3=a0;
                if (ng < 8){
#pragma unroll
                    for (int i=0;i<4;i++){
                        float w = prjXT[(pb+i)*16+t];
                        const float4* vr = (const float4*)&prjVRT[(pb+i)*16];
                        fma4(a0,w,vr[0]); fma4(a1,w,vr[1]); fma4(a2,w,vr[2]); fma4(a3,w,vr[3]);
                    }
                } else {
#pragma unroll
                    for (int i=0;i<8;i++){
                        float w = prjXT[(pb+i)*16+t];
                        const float4* vr = (const float4*)&prjVRT[(pb+i)*16];
                        fma4(a0,w,vr[0]); fma4(a1,w,vr[1]); fma4(a2,w,vr[2]); fma4(a3,w,vr[3]);
                    }
                }
                int col = ng*16 + t;
                Asc[ 0*240+col]=a0.x;            Asc[ 1*240+col]=(1<=t)?a0.y:0.f;
                Asc[ 2*240+col]=(2<=t)?a0.z:0.f; Asc[ 3*240+col]=(3<=t)?a0.w:0.f;
                Asc[ 4*240+col]=(4<=t)?a1.x:0.f; Asc[ 5*240+col]=(5<=t)?a1.y:0.f;
                Asc[ 6*240+col]=(6<=t)?a1.z:0.f; Asc[ 7*240+col]=(7<=t)?a1.w:0.f;
                Asc[ 8*240+col]=(8<=t)?a2.x:0.f; Asc[ 9*240+col]=(9<=t)?a2.y:0.f;
                Asc[10*240+col]=(10<=t)?a2.z:0.f; Asc[11*240+col]=(11<=t)?a2.w:0.f;
                Asc[12*240+col]=(12<=t)?a3.x:0.f; Asc[13*240+col]=(13<=t)?a3.y:0.f;
                Asc[14*240+col]=(14<=t)?a3.z:0.f; Asc[15*240+col]=(15<=t)?a3.w:0.f;
            } else if (j < 480){
                int jj = j-240;
                int ng = jj>>4, t = jj&15;
                int pb = s_nd[ng*5+2];
                float4 a0=make_float4(0,0,0,0), a1=a0, a2=a0, a3=a0;
                if (ng < 8){
#pragma unroll
                    for (int i=0;i<4;i++){
                        float w = prjLT[(pb+i)*16+t];
                        const float4* ul = (const float4*)&prjULT[(pb+i)*16];
                        fma4(a0,w,ul[0]); fma4(a1,w,ul[1]); fma4(a2,w,ul[2]); fma4(a3,w,ul[3]);
                    }
                } else {
#pragma unroll
                    for (int i=0;i<8;i++){
                        float w = prjLT[(pb+i)*16+t];
                        const float4* ul = (const float4*)&prjULT[(pb+i)*16];
                        fma4(a0,w,ul[0]); fma4(a1,w,ul[1]); fma4(a2,w,ul[2]); fma4(a3,w,ul[3]);
                    }
                }
                int col = ng*16 + t;
                Bsc[ 0*240+col]=a0.x;            Bsc[ 1*240+col]=(1<=t)?a0.y:0.f;
                Bsc[ 2*240+col]=(2<=t)?a0.z:0.f; Bsc[ 3*240+col]=(3<=t)?a0.w:0.f;
                Bsc[ 4*240+col]=(4<=t)?a1.x:0.f; Bsc[ 5*240+col]=(5<=t)?a1.y:0.f;
                Bsc[ 6*240+col]=(6<=t)?a1.z:0.f; Bsc[ 7*240+col]=(7<=t)?a1.w:0.f;
                Bsc[ 8*240+col]=(8<=t)?a2.x:0.f; Bsc[ 9*240+col]=(9<=t)?a2.y:0.f;
                Bsc[10*240+col]=(10<=t)?a2.z:0.f; Bsc[11*240+col]=(11<=t)?a2.w:0.f;
                Bsc[12*240+col]=(12<=t)?a3.x:0.f; Bsc[13*240+col]=(13<=t)?a3.y:0.f;
                Bsc[14*240+col]=(14<=t)?a3.z:0.f; Bsc[15*240+col]=(15<=t)?a3.w:0.f;
            } else if (j < 736){
                int jj = j-480;
                int n = jj>>4, t = jj&15;
                float4 qv = *(const float4*)&s_q[t*KPAD+4*n];
                float cvals[16];
#pragma unroll
                for (int s=0;s<16;s++){
                    float val = dot4v(*(const float4*)&s_v[s*KPAD+4*n], qv);
                    cvals[s] = (s<=t)? val : 0.f;
                }
                float acc0 = dot4v(*(const float4*)&s_leaf[(4*n+0)*4], qv);
                float acc1 = dot4v(*(const float4*)&s_leaf[(4*n+1)*4], qv);
                float acc2 = dot4v(*(const float4*)&s_leaf[(4*n+2)*4], qv);
                float acc3 = dot4v(*(const float4*)&s_leaf[(4*n+3)*4], qv);
#pragma unroll
                for (int s=0;s<16;s++){
                    float4 kv = *(const float4*)&s_k[s*KPAD+4*n];
                    float cs = cvals[s];
                    acc0 = fmaf(kv.x, cs, acc0);
                    acc1 = fmaf(kv.y, cs, acc1);
                    acc2 = fmaf(kv.z, cs, acc2);
                    acc3 = fmaf(kv.w, cs, acc3);
                }
                yl[(4*n+0)*17+t] = acc0;
                yl[(4*n+1)*17+t] = acc1;
                yl[(4*n+2)*17+t] = acc2;
                yl[(4*n+3)*17+t] = acc3;
            } else {
                int t = j-736;
                float acc = 0.f;
#pragma unroll
                for (int g=0;g<16;g++)
                    acc += dot4v(*(const float4*)&s_z[4*g], *(const float4*)&s_q[t*KPAD+4*g]);
                for (int s=0;s<=t;s++) acc += Dsc[t*16+s];
                s_den[t] = fmaxf(acc, 1e-6f);
            }
        }
        __syncthreads();

        for (int j=tid; j<2816; j+=NT){
            if (j < 1408){
                int i88 = j>>4, t = j&15;
                int info = lutP[i88]; int pb = info&255, ng=(info>>8)&255;
                float acc = 0.f;
                int wr = lutWT[i88];
                if (i88 < 32){
#pragma unroll
                    for (int u=0;u<4;u++) acc = fmaf(s_Ws[wr+u], prjXT[(pb+u)*16+t], acc);
                } else {
#pragma unroll
                    for (int u=0;u<8;u++) acc = fmaf(s_Ws[wr+u], prjXT[(pb+u)*16+t], acc);
                }
                const float4* uu4 = (const float4*)&prjULT[i88*16];
                float4 u0=uu4[0], u1=uu4[1], u2=uu4[2], u3=uu4[3];
                const int col = ng*16 + t;
                acc = fmaf(u0.x, Asc[ 0*240+col], acc);
                acc = fmaf(u0.y, Asc[ 1*240+col], acc);
                acc = fmaf(u0.z, Asc[ 2*240+col], acc);
                acc = fmaf(u0.w, Asc[ 3*240+col], acc);
                acc = fmaf(u1.x, Asc[ 4*240+col], acc);
                acc = fmaf(u1.y, Asc[ 5*240+col], acc);
                acc = fmaf(u1.z, Asc[ 6*240+col], acc);
                acc = fmaf(u1.w, Asc[ 7*240+col], acc);
                acc = fmaf(u2.x, Asc[ 8*240+col], acc);
                acc = fmaf(u2.y, Asc[ 9*240+col], acc);
                acc = fmaf(u2.z, Asc[10*240+col], acc);
                acc = fmaf(u2.w, Asc[11*240+col], acc);
                acc = fmaf(u3.x, Asc[12*240+col], acc);
                acc = fmaf(u3.y, Asc[13*240+col], acc);
                acc = fmaf(u3.z, Asc[14*240+col], acc);
                acc = fmaf(u3.w, Asc[15*240+col], acc);
                TT[i88*17+t] = acc;
            } else {
                int jj = j-1408;
                int i88 = jj>>4, t = jj&15;
                int info = lutP[i88]; int pb = info&255, ng=(info>>8)&255;
                float acc = 0.f;
                int wc = lutWB[i88];
                if (i88 < 32){
#pragma unroll
                    for (int u=0;u<4;u++) acc = fmaf(s_Ws[wc+u*4], prjLT[(pb+u)*16+t], acc);
                } else {
#pragma unroll
                    for (int u=0;u<8;u++) acc = fmaf(s_Ws[wc+u*8], prjLT[(pb+u)*16+t], acc);
                }
                const float4* vv4 = (const float4*)&prjVRT[i88*16];
                float4 v0=vv4[0], v1=vv4[1], v2=vv4[2], v3=vv4[3];
                const int col = ng*16 + t;
                acc = fmaf(v0.x, Bsc[ 0*240+col], acc);
                acc = fmaf(v0.y, Bsc[ 1*240+col], acc);
                acc = fmaf(v0.z, Bsc[ 2*240+col], acc);
                acc = fmaf(v0.w, Bsc[ 3*240+col], acc);
                acc = fmaf(v1.x, Bsc[ 4*240+col], acc);
                acc = fmaf(v1.y, Bsc[ 5*240+col], acc);
                acc = fmaf(v1.z, Bsc[ 6*240+col], acc);
                acc = fmaf(v1.w, Bsc[ 7*240+col], acc);
                acc = fmaf(v2.x, Bsc[ 8*240+col], acc);
                acc = fmaf(v2.y, Bsc[ 9*240+col], acc);
                acc = fmaf(v2.z, Bsc[10*240+col], acc);
                acc = fmaf(v2.w, Bsc[11*240+col], acc);
                acc = fmaf(v3.x, Bsc[12*240+col], acc);
                acc = fmaf(v3.y, Bsc[13*240+col], acc);
                acc = fmaf(v3.z, Bsc[14*240+col], acc);
                acc = fmaf(v3.w, Bsc[15*240+col], acc);
                TBB[i88*17+t] = acc;
            }
        }
        __syncthreads();

        for (int j=tid; j<1024; j+=NT){
            int d = j&63, t = j>>6;
            float y = yl[d*17+t];
#pragma unroll
            for (int l=0;l<4;l++){
                const int bs = 4<<l;
                const int r  = (l==0)?4:8;
                const int n = d >> (3+l);
                const int loc = d & (2*bs - 1);
                const int pb = Knro(l) + n*r;
                const int bso = Kbso(l);
                if (loc < bs){
                    const float* u = sUL + bso + loc*r;
#pragma unroll
                    for (int i=0;i<8;i++){
                        if (i < r) y = fmaf(u[i], TT[(pb+i)*17+t], y);
                    }
                } else {
                    const float* u = sUR + bso + (loc-bs)*r;
#pragma unroll
                    for (int i=0;i<8;i++){
                        if (i < r) y = fmaf(u[i], TBB[(pb+i)*17+t], y);
                    }
                }
            }
            float o = y / s_den[t];
            __nv_bfloat16 h = __float2bfloat16(o);
            g_oh[(size_t)t*DH + d] = h;
            g_ol[(size_t)t*DH + d] = __float2bfloat16(o - __bfloat162float(h));
        }
    }
}

// ---------------- output GEMM via mma.sync bf16x3 ----------------
#define WA 72
#define WB 136
#define WO_BYTES ((128*WA*2 + 64*WB*2)*2)
__global__ __launch_bounds__(256) void wo_mma_kernel(float* __restrict__ out){
    extern __shared__ __nv_bfloat16 ws[];
    __nv_bfloat16* sAh = ws;
    __nv_bfloat16* sAl = sAh + 128*WA;
    __nv_bfloat16* sBh = sAl + 128*WA;
    __nv_bfloat16* sBl = sBh + 64*WB;

    const int tid = threadIdx.x;
    const int wid = tid >> 5, lane = tid & 31;
    const int wy = wid & 3, wx = wid >> 2;
    const int rb = blockIdx.x * 128, cb = blockIdx.y * 128;

#pragma unroll
    for (int i=0;i<4;i++){
        int idx = tid + i*256;
        int row = idx >> 3, c8 = idx & 7;
        cp_async16(sAh + row*WA + c8*8, g_ah + (size_t)(rb+row)*DH + c8*8);
        cp_async16(sAl + row*WA + c8*8, g_al + (size_t)(rb+row)*DH + c8*8);
    }
#pragma unroll
    for (int i=0;i<4;i++){
        int idx = tid + i*256;
        int k = idx >> 4, c16 = idx & 15;
        cp_async16(sBh + k*WB + c16*8, g_woh + (size_t)k*DM + cb + c16*8);
        cp_async16(sBl + k*WB + c16*8, g_wol + (size_t)k*DM + cb + c16*8);
    }
    asm volatile("cp.async.commit_group;\n");
    asm volatile("cp.async.wait_group 0;\n");
    __syncthreads();

    float acc[2][8][4];
#pragma unroll
    for (int m=0;m<2;m++)
#pragma unroll
        for (int n=0;n<8;n++){ acc[m][n][0]=acc[m][n][1]=acc[m][n][2]=acc[m][n][3]=0.f; }

#pragma unroll
    for (int k0=0;k0<64;k0+=16){
        unsigned ah[2][4], al[2][4];
#pragma unroll
        for (int mt=0;mt<2;mt++){
            const __nv_bfloat16* ap = sAh + (wy*32 + mt*16 + (lane&15))*WA + k0 + (lane>>4)*8;
            ldmx4(ah[mt][0],ah[mt][1],ah[mt][2],ah[mt][3], ap);
            const __nv_bfloat16* ap2 = sAl + (wy*32 + mt*16 + (lane&15))*WA + k0 + (lane>>4)*8;
            ldmx4(al[mt][0],al[mt][1],al[mt][2],al[mt][3], ap2);
        }
#pragma unroll
        for (int nt=0;nt<4;nt++){
            unsigned bh0,bh1,bh2,bh3, bl0,bl1,bl2,bl3;
            const __nv_bfloat16* bp = sBh + (k0 + (lane&15))*WB + wx*64 + nt*16 + (lane>>4)*8;
            ldmx4t(bh0,bh1,bh2,bh3, bp);
            const __nv_bfloat16* bp2 = sBl + (k0 + (lane&15))*WB + wx*64 + nt*16 + (lane>>4)*8;
            ldmx4t(bl0,bl1,bl2,bl3, bp2);
#pragma unroll
            for (int mt=0;mt<2;mt++){
                mma16816(acc[mt][2*nt],   ah[mt][0],ah[mt][1],ah[mt][2],ah[mt][3], bh0,bh1);
                mma16816(acc[mt][2*nt],   ah[mt][0],ah[mt][1],ah[mt][2],ah[mt][3], bl0,bl1);
                mma16816(acc[mt][2*nt],   al[mt][0],al[mt][1],al[mt][2],al[mt][3], bh0,bh1);
                mma16816(acc[mt][2*nt+1], ah[mt][0],ah[mt][1],ah[mt][2],ah[mt][3], bh2,bh3);
                mma16816(acc[mt][2*nt+1], ah[mt][0],ah[mt][1],ah[mt][2],ah[mt][3], bl2,bl3);
                mma16816(acc[mt][2*nt+1], al[mt][0],al[mt][1],al[mt][2],al[mt][3], bh2,bh3);
            }
        }
    }

#pragma unroll
    for (int mt=0;mt<2;mt++){
        int row = rb + wy*32 + mt*16 + (lane>>2);
#pragma unroll
        for (int nt=0;nt<8;nt++){
            int col = cb + wx*64 + nt*8 + (lane&3)*2;
            *(float2*)(out + (size_t)row*DM + col)     = make_float2(acc[mt][nt][0], acc[mt][nt][1]);
            *(float2*)(out + (size_t)(row+8)*DM + col) = make_float2(acc[mt][nt][2], acc[mt][nt][3]);
        }
    }
}

extern "C" void kernel_launch(void* const* d_in, const int* in_sizes, int n_in,
                              void* d_out, int out_size){
    (void)in_sizes; (void)n_in; (void)out_size;
    const float* x  = (const float*)d_in[0];
    const float* Wq = (const float*)d_in[1];
    const float* Wk = (const float*)d_in[2];
    const float* Wv = (const float*)d_in[3];
    const float* Wo = (const float*)d_in[4];
    BasePtrs bp;
    for(int i=0;i<16;i++) bp.p[i] = (const float*)d_in[5+i];
    float* out = (float*)d_out;

    cudaFuncSetAttribute(qkv_mma_kernel,    cudaFuncAttributeMaxDynamicSharedMemorySize, QKV_BYTES);
    cudaFuncSetAttribute(chunk_sum4_kernel, cudaFuncAttributeMaxDynamicSharedMemorySize, P1_BYTES);
    cudaFuncSetAttribute(chunk_scan_kernel, cudaFuncAttributeMaxDynamicSharedMemorySize, P3_BYTES);
    cudaFuncSetAttribute(wo_mma_kernel,     cudaFuncAttributeMaxDynamicSharedMemorySize, WO_BYTES);

    wprep_kernel<<<(DM*NW + DH*DM)/256, 256>>>(Wq, Wk, Wv, Wo);
    qkv_mma_kernel<<<NTOK/128, 256, QKV_BYTES>>>(x);
    chunk_sum4_kernel<<<BB*NGRP, NT, P1_BYTES>>>(bp);
    midscan_kernel<<<dim3(NST/128, BB), 128>>>();
    chunk_scan_kernel<<<BB*NCH/2, NT, P3_BYTES>>>(bp);
    wo_mma_kernel<<<dim3(NTOK/128, DM/128), 256, WO_BYTES>>>(out);
}

// round 12
// speedup vs baseline: 1.0518x; 1.0518x over previous
#include <cuda_runtime.h>
#include <cuda_bf16.h>
#include <math.h>

#define TSEQ 2048
#define BB 8
#define DH 64
#define DM 1024
#define NTOK (BB*TSEQ)
#define CCH 16
#define NCH (TSEQ/CCH)   /* 128 */
#define NST 896
#define KPAD 68
#define NT 512
#define NW 192
#define NGRP 32
#define PSTR 97

// scratch (device globals -- no allocation allowed)
__device__ float g_q[NTOK*DH];
__device__ float g_k[NTOK*DH];
__device__ float g_v[NTOK*DH];
__device__ float g_prefix[BB*NCH*NST];
__device__ float g_gtot[BB*NGRP*NST];
__device__ float g_goff[BB*NGRP*NST];
__device__ __nv_bfloat16 g_wh[DM*NW];
__device__ __nv_bfloat16 g_wl[DM*NW];
__device__ __nv_bfloat16 g_ah[NTOK*DH];
__device__ __nv_bfloat16 g_al[NTOK*DH];
__device__ __nv_bfloat16 g_woh[DH*DM];
__device__ __nv_bfloat16 g_wol[DH*DM];

struct BasePtrs { const float* p[16]; };

// ---------------- helpers ----------------
__device__ __forceinline__ void cp_async16(void* sptr, const void* gptr){
    unsigned s = (unsigned)__cvta_generic_to_shared(sptr);
    asm volatile("cp.async.ca.shared.global [%0], [%1], 16;" :: "r"(s), "l"(gptr));
}
__device__ __forceinline__ float dot4v(float4 a, float4 b){
    return fmaf(a.x,b.x, fmaf(a.y,b.y, fmaf(a.z,b.z, a.w*b.w)));
}
__device__ __forceinline__ void fma4(float4 &acc, float s, float4 v){
    acc.x = fmaf(s, v.x, acc.x); acc.y = fmaf(s, v.y, acc.y);
    acc.z = fmaf(s, v.z, acc.z); acc.w = fmaf(s, v.w, acc.w);
}
__device__ __forceinline__ unsigned smem_u32(const void* p){
    return (unsigned)__cvta_generic_to_shared(p);
}
__device__ __forceinline__ void ldmx4(unsigned &r0, unsigned &r1, unsigned &r2, unsigned &r3, const void* p){
    asm volatile("ldmatrix.sync.aligned.m8n8.x4.shared.b16 {%0,%1,%2,%3}, [%4];"
        : "=r"(r0),"=r"(r1),"=r"(r2),"=r"(r3) : "r"(smem_u32(p)));
}
__device__ __forceinline__ void ldmx4t(unsigned &r0, unsigned &r1, unsigned &r2, unsigned &r3, const void* p){
    asm volatile("ldmatrix.sync.aligned.m8n8.x4.trans.shared.b16 {%0,%1,%2,%3}, [%4];"
        : "=r"(r0),"=r"(r1),"=r"(r2),"=r"(r3) : "r"(smem_u32(p)));
}
__device__ __forceinline__ void mma16816(float* c, unsigned a0,unsigned a1,unsigned a2,unsigned a3,
                                         unsigned b0, unsigned b1){
    asm volatile("mma.sync.aligned.m16n8k16.row.col.f32.bf16.bf16.f32 "
        "{%0,%1,%2,%3}, {%4,%5,%6,%7}, {%8,%9}, {%0,%1,%2,%3};"
        : "+f"(c[0]),"+f"(c[1]),"+f"(c[2]),"+f"(c[3])
        : "r"(a0),"r"(a1),"r"(a2),"r"(a3),"r"(b0),"r"(b1));
}

__device__ __forceinline__ int Knro(int l){ return (l==0)?0:(l==1)?32:(l==2)?64:80; }
__device__ __forceinline__ int Kwso(int l){ return (l==0)?0:(l==1)?128:(l==2)?384:512; }
__device__ __forceinline__ int Kbso(int l){ return (l==0)?0:(l==1)?16:(l==2)?80:208; }
__device__ __forceinline__ int Knoff(int l){ return (l==0)?0:(l==1)?8:(l==2)?12:14; }

// ---------------- weight split prep ----------------
__global__ __launch_bounds__(256) void wprep_kernel(const float* __restrict__ Wq,
                                                    const float* __restrict__ Wk,
                                                    const float* __restrict__ Wv,
                                                    const float* __restrict__ Wo){
    int idx = blockIdx.x*256 + threadIdx.x;
    if (idx < DM*NW){
        int k = idx / NW, n = idx - k*NW;
        const float* W = (n<64)?Wq:(n<128?Wk:Wv);
        float w = W[(size_t)k*DH + (n&63)];
        __nv_bfloat16 hi = __float2bfloat16(w);
        g_wh[idx] = hi;
        g_wl[idx] = __float2bfloat16(w - __bfloat162float(hi));
    } else {
        int j = idx - DM*NW;
        float w = Wo[j];
        __nv_bfloat16 hi = __float2bfloat16(w);
        g_woh[j] = hi;
        g_wol[j] = __float2bfloat16(w - __bfloat162float(hi));
    }
}

// ---------------- QKV via mma.sync bf16x3 (R10 config: BM=64, 2 blk/SM) ----------------
#define ASTR 24
#define BSTR 200
__global__ __launch_bounds__(256) void qkv_mma_kernel(const float* __restrict__ x){
    __shared__ __nv_bfloat16 sAh[2][64*ASTR];
    __shared__ __nv_bfloat16 sAl[2][64*ASTR];
    __shared__ __nv_bfloat16 sBh[2][16*BSTR];
    __shared__ __nv_bfloat16 sBl[2][16*BSTR];

    const int tid = threadIdx.x;
    const int wid = tid >> 5, lane = tid & 31;
    const int wy = wid & 3, wx = wid >> 2;
    const int rb = blockIdx.x * 64;
    const int arow = tid >> 2, akg = tid & 3;

    float acc[12][4];
#pragma unroll
    for (int i=0;i<12;i++){ acc[i][0]=acc[i][1]=acc[i][2]=acc[i][3]=0.f; }

    auto loadB = [&](int k0, int buf){
#pragma unroll
        for (int i=0;i<3;i++){
            int idx = tid + i*256;
            int m2 = (idx >= 384);
            int id2 = idx - m2*384;
            int r = id2 / 24, c8 = id2 - r*24;
            const __nv_bfloat16* src = (m2 ? g_wl : g_wh) + (size_t)(k0+r)*NW + c8*8;
            __nv_bfloat16* dst = (m2 ? sBl[buf] : sBh[buf]) + r*BSTR + c8*8;
            cp_async16(dst, src);
        }
    };
    auto storeA = [&](float4 v, int buf){
        __nv_bfloat16 h0=__float2bfloat16(v.x), h1=__float2bfloat16(v.y),
                      h2=__float2bfloat16(v.z), h3=__float2bfloat16(v.w);
        float l0 = v.x-__bfloat162float(h0), l1 = v.y-__bfloat162float(h1),
              l2 = v.z-__bfloat162float(h2), l3 = v.w-__bfloat162float(h3);
        __nv_bfloat162 hh0 = __halves2bfloat162(h0,h1), hh1 = __halves2bfloat162(h2,h3);
        __nv_bfloat162 ll0 = __floats2bfloat162_rn(l0,l1), ll1 = __floats2bfloat162_rn(l2,l3);
        uint2 hu = make_uint2(*(unsigned*)&hh0, *(unsigned*)&hh1);
        uint2 lu = make_uint2(*(unsigned*)&ll0, *(unsigned*)&ll1);
        *(uint2*)&sAh[buf][arow*ASTR + akg*4] = hu;
        *(uint2*)&sAl[buf][arow*ASTR + akg*4] = lu;
    };

    const float* xrow = x + (size_t)(rb+arow)*DM + akg*4;
    float4 av = *(const float4*)xrow;
    loadB(0, 0);
    asm volatile("cp.async.commit_group;\n");
    storeA(av, 0);
    asm volatile("cp.async.wait_group 0;\n");
    __syncthreads();
    av = *(const float4*)(xrow + 16);   // prefetch stage 1

    const int a_off = (wy*16 + (lane&15))*ASTR + (lane>>4)*8;
    const int b_off = (lane&15)*BSTR + wx*96 + (lane>>4)*8;

    for(int kt=0; kt<64; kt++){
        const int buf = kt & 1;
        if (kt < 63){
            loadB((kt+1)*16, buf^1);
            asm volatile("cp.async.commit_group;\n");
            storeA(av, buf^1);
            if (kt < 62)
                av = *(const float4*)(xrow + (kt+2)*16);
        }
        unsigned ah0,ah1,ah2,ah3, al0,al1,al2,al3;
        ldmx4(ah0,ah1,ah2,ah3, sAh[buf] + a_off);
        ldmx4(al0,al1,al2,al3, sAl[buf] + a_off);
#pragma unroll
        for(int nb=0; nb<6; nb++){
            unsigned bh0,bh1,bh2,bh3, bl0,bl1,bl2,bl3;
            ldmx4t(bh0,bh1,bh2,bh3, sBh[buf] + b_off + nb*16);
            ldmx4t(bl0,bl1,bl2,bl3, sBl[buf] + b_off + nb*16);
            mma16816(acc[2*nb],   ah0,ah1,ah2,ah3, bh0,bh1);
            mma16816(acc[2*nb],   ah0,ah1,ah2,ah3, bl0,bl1);
            mma16816(acc[2*nb],   al0,al1,al2,al3, bh0,bh1);
            mma16816(acc[2*nb+1], ah0,ah1,ah2,ah3, bh2,bh3);
            mma16816(acc[2*nb+1], ah0,ah1,ah2,ah3, bl2,bl3);
            mma16816(acc[2*nb+1], al0,al1,al2,al3, bh2,bh3);
        }
        if (kt < 63){
            asm volatile("cp.async.wait_group 0;\n");
        }
        __syncthreads();
    }

    const int row0 = rb + wy*16 + (lane>>2);
#pragma unroll
    for (int t=0; t<12; t++){
        int col = wx*96 + t*8 + (lane&3)*2;
        bool act = (col < 128);
        float* base = (col < 64) ? g_q : (col < 128 ? g_k : g_v);
        int cc = col & 63;
        float v0 = acc[t][0], v1 = acc[t][1], v2 = acc[t][2], v3 = acc[t][3];
        if (act){
            v0 = (v0>0.f)? v0+1.f : expf(v0);
            v1 = (v1>0.f)? v1+1.f : expf(v1);
            v2 = (v2>0.f)? v2+1.f : expf(v2);
            v3 = (v3>0.f)? v3+1.f : expf(v3);
        }
        base[(size_t)row0*DH + cc]       = v0;
        base[(size_t)row0*DH + cc + 1]   = v1;
        base[(size_t)(row0+8)*DH + cc]   = v2;
        base[(size_t)(row0+8)*DH + cc+1] = v3;
    }
}

// =====================================================================
// shared LUT builders
// =====================================================================
__device__ __forceinline__ void build_node_lut(int* s_nd, int tid){
    if (tid < 15){
        int l = (tid<8)?0:(tid<12)?1:(tid<14)?2:3;
        int n = tid - Knoff(l);
        int bs = 4<<l, r = (l==0)?4:8;
        s_nd[tid*5+0]=bs; s_nd[tid*5+1]=r; s_nd[tid*5+2]=Knro(l)+n*r;
        s_nd[tid*5+3]=2*bs*n; s_nd[tid*5+4]=Kbso(l);
    }
}
__device__ __forceinline__ void build_ws_lut(int* s_lutAB, int tid, int nthr){
    for (int m = tid; m < 576; m += nthr){
        int l = (m<128)?0:(m<384)?1:(m<512)?2:3;
        int r = (l==0)?4:8;
        int rem = m - Kwso(l);
        int rr2 = r*r;
        int n = rem / rr2;
        int ij = rem - n*rr2;
        int i = ij / r, j = ij - i*r;
        int pb = Knro(l) + n*r;
        s_lutAB[m] = (pb+i) | ((pb+j)<<16);
    }
}
__device__ __forceinline__ void build_chunk_lut(int* s_ck, int tid){
    if (tid < 20){
        int c = tid, m, dd0=0, ext=0, ec=0;
        if (c < 13){ m = c; }
        else if (c == 13){ m=12; dd0=8; ext=1; ec=0; }
        else if (c == 14){ m=13; }
        else if (c == 15){ m=13; dd0=8; ext=1; ec=1; }
        else if (c == 16){ m=14; }
        else { m=14; dd0=8*(c-16); ext=1; ec=c-15; }
        s_ck[c] = m | (dd0<<8) | (ext<<16) | (ec<<20);
    }
}

// =====================================================================
// Pass 1: per-group (4 chunks) sums; prj transposed [16][PSTR]
// =====================================================================
#define P1_FLOATS (2176 + 2*16*PSTR + 928 + 1280)
#define P1_BYTES (P1_FLOATS*4 + (75+576+20)*4)
__global__ __launch_bounds__(512,2) void chunk_sum4_kernel(BasePtrs bp){
    extern __shared__ float sm[];
    float* s_k    = sm;
    float* s_v    = s_k + 16*KPAD;
    float* prjULT = s_v + 16*KPAD;
    float* prjVRT = prjULT + 16*PSTR;
    float* sUL    = prjVRT + 16*PSTR;
    float* sVR    = sUL + 464;
    float* extP   = sVR + 464;
    int*   s_nd   = (int*)(extP + 1280);
    int*   lutAB  = s_nd + 75;
    int*   s_ck   = lutAB + 576;

    const int tid = threadIdx.x;
    const int blk = blockIdx.x;
    const int b = blk / NGRP, grp = blk % NGRP;

    for (int i=tid;i<464;i+=NT){
        int l = (i<16)?0:(i<80)?1:(i<208)?2:3;
        int off = i - Kbso(l);
        sUL[i] = bp.p[l][off];
        sVR[i] = bp.p[4+l][off];
    }
    build_node_lut(s_nd, tid);
    build_ws_lut(lutAB, tid, NT);
    build_chunk_lut(s_ck, tid);
    __syncthreads();

    float sreg[2][4];

    for (int j=0;j<4;j++){
        const int c = grp*4 + j;
        const float* gk = g_k + ((size_t)b*TSEQ + c*CCH)*DH;
        const float* gv = g_v + ((size_t)b*TSEQ + c*CCH)*DH;
        if (tid < 512){
            int arr = tid>>8;
            int rem = tid & 255; int row = rem>>4, g = rem&15;
            const float* src = (arr==0?gk:gv) + row*64 + g*4;
            float* dst = (arr==0?s_k:s_v) + row*KPAD + g*4;
            *(float4*)dst = *(const float4*)src;
        }
        __syncthreads();

        if (tid < 320){
            int cd = s_ck[tid>>4]; int s = tid&15;
            int m = cd & 31, dd0 = (cd>>8)&63, isext=(cd>>16)&1, ec=(cd>>20)&7;
            int bs=s_nd[m*5], r=s_nd[m*5+1], pb=s_nd[m*5+2], topo=s_nd[m*5+3], bso=s_nd[m*5+4];
            const float* kt = s_k + s*KPAD + topo + dd0;
            const float* vb = s_v + s*KPAD + topo + bs + dd0;
            const float* Ub = sUL + bso + dd0*r;
            const float* Wb = sVR + bso + dd0*r;
            if (r == 4){
                float4 aU=make_float4(0,0,0,0), aV=aU;
#pragma unroll
                for (int d=0; d<4; d++){
                    float kd=kt[d], vd=vb[d];
                    float4 u=*(const float4*)(Ub+d*4), w=*(const float4*)(Wb+d*4);
                    fma4(aU,kd,u); fma4(aV,vd,w);
                }
                float au[4]={aU.x,aU.y,aU.z,aU.w}, avv[4]={aV.x,aV.y,aV.z,aV.w};
#pragma unroll
                for (int i=0;i<4;i++){
                    prjULT[s*PSTR + pb+i]=au[i];
                    prjVRT[s*PSTR + pb+i]=avv[i];
                }
            } else {
                float aU[8], aV[8];
#pragma unroll
                for (int i=0;i<8;i++){ aU[i]=0.f; aV[i]=0.f; }
#pragma unroll
                for (int d=0; d<8; d++){
                    float kd=kt[d], vd=vb[d];
                    float4 u0=*(const float4*)(Ub+d*8), u1=*(const float4*)(Ub+d*8+4);
                    float4 w0=*(const float4*)(Wb+d*8), w1=*(const float4*)(Wb+d*8+4);
                    aU[0]=fmaf(kd,u0.x,aU[0]); aU[1]=fmaf(kd,u0.y,aU[1]); aU[2]=fmaf(kd,u0.z,aU[2]); aU[3]=fmaf(kd,u0.w,aU[3]);
                    aU[4]=fmaf(kd,u1.x,aU[4]); aU[5]=fmaf(kd,u1.y,aU[5]); aU[6]=fmaf(kd,u1.z,aU[6]); aU[7]=fmaf(kd,u1.w,aU[7]);
                    aV[0]=fmaf(vd,w0.x,aV[0]); aV[1]=fmaf(vd,w0.y,aV[1]); aV[2]=fmaf(vd,w0.z,aV[2]); aV[3]=fmaf(vd,w0.w,aV[3]);
                    aV[4]=fmaf(vd,w1.x,aV[4]); aV[5]=fmaf(vd,w1.y,aV[5]); aV[6]=fmaf(vd,w1.z,aV[6]); aV[7]=fmaf(vd,w1.w,aV[7]);
                }
                if (!isext){
#pragma unroll
                    for (int i=0;i<8;i++){
                        prjULT[s*PSTR + pb+i]=aU[i];
                        prjVRT[s*PSTR + pb+i]=aV[i];
                    }
                } else {
#pragma unroll
                    for (int i=0;i<8;i++){
                        extP[((0*5+ec)*8+i)*16+s]=aU[i];
                        extP[((1*5+ec)*8+i)*16+s]=aV[i];
                    }
                }
            }
        }
        __syncthreads();
        if (tid < 256){
            int a=tid>>7, i=(tid>>4)&7, s=tid&15;
            float* base = prjULT + a*(16*PSTR);
            base[s*PSTR + 64+i] += extP[((a*5+0)*8+i)*16+s];
            base[s*PSTR + 72+i] += extP[((a*5+1)*8+i)*16+s];
            base[s*PSTR + 80+i] += extP[((a*5+2)*8+i)*16+s] + extP[((a*5+3)*8+i)*16+s] + extP[((a*5+4)*8+i)*16+s];
        }
        __syncthreads();

#pragma unroll
        for (int o=0;o<2;o++){
            int e = tid + o*512;
            if (e < NST){
                float acc = 0.f;
                if (e < 256){
                    int n=e>>4, i=(e>>2)&3, j2=e&3;
                    int ki=4*n+i, vi=4*n+j2;
#pragma unroll
                    for (int s=0;s<CCH;s++) acc = fmaf(s_k[s*KPAD+ki], s_v[s*KPAD+vi], acc);
                } else if (e < 832){
                    int m = e-256;
                    int ab = lutAB[m]; int a = ab & 0xffff, b3 = ab >> 16;
#pragma unroll
                    for (int s=0;s<16;s++)
                        acc = fmaf(prjULT[s*PSTR+a], prjVRT[s*PSTR+b3], acc);
                } else {
                    int d = e-832;
#pragma unroll
                    for (int s=0;s<CCH;s++) acc += s_k[s*KPAD+d];
                }
                sreg[o][j] = acc;
            }
        }
        __syncthreads();
    }

#pragma unroll
    for (int o=0;o<2;o++){
        int e = tid + o*512;
        if (e < NST){
            float run = 0.f;
#pragma unroll
            for (int j=0;j<4;j++){
                g_prefix[(size_t)(blk*4+j)*NST + e] = run;
                run += sreg[o][j];
            }
            g_gtot[(size_t)blk*NST + e] = run;
        }
    }
}

// =====================================================================
// Pass 2: exclusive prefix over 32 group totals per batch (MLP=32)
// =====================================================================
__global__ __launch_bounds__(128) void midscan_kernel(){
    const int b = blockIdx.y;
    const int e = blockIdx.x*128 + threadIdx.x;
    const float* gt = g_gtot + (size_t)b*NGRP*NST + e;
    float*       go = g_goff + (size_t)b*NGRP*NST + e;
    float v[NGRP];
#pragma unroll
    for (int j=0;j<NGRP;j++) v[j] = gt[(size_t)j*NST];
    float run = 0.f;
#pragma unroll
    for (int j=0;j<NGRP;j++){ go[(size_t)j*NST] = run; run += v[j]; }
}

// =====================================================================
// Pass 3: fully parallel intra-chunk attention, 2 chunks per block
// =====================================================================
#define P3_FLOATS (3264 + 5632 + 1856 + 896 + 3840 + 3840 + 2560 + 256 + 16 + 1496 + 1496 + 1088)
#define P3_BYTES (P3_FLOATS*4 + (75 + 88*3 + 20)*4)
__global__ __launch_bounds__(512,2) void chunk_scan_kernel(BasePtrs bp){
    extern __shared__ float sm[];
    float* s_k    = sm;
    float* s_v    = s_k + 16*KPAD;
    float* s_q    = s_v + 16*KPAD;
    float* prjULT = s_q + 16*KPAD;
    float* prjVRT = prjULT + 1408;
    float* prjXT  = prjVRT + 1408;
    float* prjLT  = prjXT + 1408;
    float* sUL    = prjLT + 1408;
    float* sVR    = sUL + 464;
    float* sUR    = sVR + 464;
    float* sVL    = sUR + 464;
    float* s_leaf = sVL + 464;
    float* s_Ws   = s_leaf + 256;
    float* s_z    = s_Ws + 576;
    float* Asc    = s_z + 64;          // [16 s][240 col]
    float* Bsc    = Asc + 3840;
    float* extP   = Bsc + 3840;
    float* Dsc    = extP + 2560;
    float* s_den  = Dsc + 256;
    float* TT     = s_den + 16;
    float* TBB    = TT + 1496;
    float* yl     = TBB + 1496;
    int*   s_nd   = (int*)(yl + 1088);
    int*   lutP   = s_nd + 75;
    int*   lutWT  = lutP + 88;
    int*   lutWB  = lutWT + 88;
    int*   s_ck   = lutWB + 88;

    const int tid = threadIdx.x;
    const int blk = blockIdx.x;
    const int b = blk / (NCH/2), cp = blk % (NCH/2);

    for (int i=tid;i<464;i+=NT){
        int l = (i<16)?0:(i<80)?1:(i<208)?2:3;
        int off = i - Kbso(l);
        sUL[i] = bp.p[l   ][off];
        sVR[i] = bp.p[4+l ][off];
        sUR[i] = bp.p[8+l ][off];
        sVL[i] = bp.p[12+l][off];
    }
    build_node_lut(s_nd, tid);
    build_chunk_lut(s_ck, tid);
    if (tid < 88){
        int i88 = tid;
        int l = (i88<32)?0:(i88<64)?1:(i88<80)?2:3;
        int r = (l==0)?4:8;
        int rem = i88 - Knro(l);
        int n = rem / r, i = rem - n*r;
        int pb = Knro(l) + n*r;
        int ng = Knoff(l) + n;
        lutP[i88]  = pb | (ng<<8) | (r<<16);
        lutWT[i88] = Kwso(l) + n*r*r + i*r;
        lutWB[i88] = Kwso(l) + n*r*r + i;
    }

    for (int cc=0; cc<2; cc++){
        const int c = cp*2 + cc;
        const int ci = b*NCH + c;
        const float* gk = g_k + ((size_t)b*TSEQ + c*CCH)*DH;
        const float* gv = g_v + ((size_t)b*TSEQ + c*CCH)*DH;
        const float* gq = g_q + ((size_t)b*TSEQ + c*CCH)*DH;
        __nv_bfloat16* g_oh = g_ah + ((size_t)b*TSEQ + c*CCH)*DH;
        __nv_bfloat16* g_ol = g_al + ((size_t)b*TSEQ + c*CCH)*DH;

        for (int i=tid;i<768;i+=NT){
            int arr = i>>8;
            int rem = i & 255; int row = rem>>4, g = rem&15;
            const float* src = (arr==0?gk:(arr==1?gv:gq)) + row*64 + g*4;
            float* dst = (arr==0?s_k:(arr==1?s_v:s_q)) + row*KPAD + g*4;
            *(float4*)dst = *(const float4*)src;
        }
        {
            const float* gp = g_prefix + (size_t)ci*NST;
            const float* gof = g_goff + ((size_t)(b*NGRP) + (c>>2))*NST;
            for (int e=tid;e<NST;e+=NT){
                float vle = gp[e] + gof[e];
                if (e<256) s_leaf[e]=vle;
                else if (e<832) s_Ws[e-256]=vle;
                else s_z[e-832]=vle;
            }
        }
        __syncthreads();

        if (tid < 320){
            int cd = s_ck[tid>>4]; int s = tid&15;
            int m = cd & 31, dd0 = (cd>>8)&63, isext=(cd>>16)&1, ec=(cd>>20)&7;
            int bs=s_nd[m*5], r=s_nd[m*5+1], pb=s_nd[m*5+2], topo=s_nd[m*5+3], bso=s_nd[m*5+4];
            const float* kt = s_k + s*KPAD + topo + dd0;
            const float* vb = s_v + s*KPAD + topo + bs + dd0;
            const float* qt = s_q + s*KPAD + topo + dd0;
            const float* qb = s_q + s*KPAD + topo + bs + dd0;
            const float* Ub = sUL + bso + dd0*r;
            const float* Wb = sVR + bso + dd0*r;
            const float* Xb = sVL + bso + dd0*r;
            if (r == 4){
                float4 aU=make_float4(0,0,0,0), aV=aU, aX=aU, aL=aU;
#pragma unroll
                for (int d=0; d<4; d++){
                    float kd=kt[d], vd=vb[d], qtd=qt[d], qbd=qb[d];
                    float4 u=*(const float4*)(Ub+d*4), w=*(const float4*)(Wb+d*4), x=*(const float4*)(Xb+d*4);
                    fma4(aU,kd,u); fma4(aV,vd,w); fma4(aX,qbd,w); fma4(aL,qtd,x);
                }
                float t0[4]={aU.x,aU.y,aU.z,aU.w}, t1[4]={aV.x,aV.y,aV.z,aV.w};
                float t2[4]={aX.x,aX.y,aX.z,aX.w}, t3[4]={aL.x,aL.y,aL.z,aL.w};
#pragma unroll
                for (int i=0;i<4;i++){
                    prjULT[(pb+i)*16+s]=t0[i];
                    prjVRT[(pb+i)*16+s]=t1[i];
                    prjXT [(pb+i)*16+s]=t2[i];
                    prjLT [(pb+i)*16+s]=t3[i];
                }
            } else {
                {
                    float aU[8], aV[8];
#pragma unroll
                    for (int i=0;i<8;i++){ aU[i]=0.f; aV[i]=0.f; }
#pragma unroll
                    for (int d=0; d<8; d++){
                        float kd=kt[d], vd=vb[d];
                        float4 u0=*(const float4*)(Ub+d*8), u1=*(const float4*)(Ub+d*8+4);
                        float4 w0=*(const float4*)(Wb+d*8), w1=*(const float4*)(Wb+d*8+4);
                        aU[0]=fmaf(kd,u0.x,aU[0]); aU[1]=fmaf(kd,u0.y,aU[1]); aU[2]=fmaf(kd,u0.z,aU[2]); aU[3]=fmaf(kd,u0.w,aU[3]);
                        aU[4]=fmaf(kd,u1.x,aU[4]); aU[5]=fmaf(kd,u1.y,aU[5]); aU[6]=fmaf(kd,u1.z,aU[6]); aU[7]=fmaf(kd,u1.w,aU[7]);
                        aV[0]=fmaf(vd,w0.x,aV[0]); aV[1]=fmaf(vd,w0.y,aV[1]); aV[2]=fmaf(vd,w0.z,aV[2]); aV[3]=fmaf(vd,w0.w,aV[3]);
                        aV[4]=fmaf(vd,w1.x,aV[4]); aV[5]=fmaf(vd,w1.y,aV[5]); aV[6]=fmaf(vd,w1.z,aV[6]); aV[7]=fmaf(vd,w1.w,aV[7]);
                    }
                    if (!isext){
#pragma unroll
                        for (int i=0;i<8;i++){ prjULT[(pb+i)*16+s]=aU[i]; prjVRT[(pb+i)*16+s]=aV[i]; }
                    } else {
#pragma unroll
                        for (int i=0;i<8;i++){
                            extP[((0*5+ec)*8+i)*16+s]=aU[i];
                            extP[((1*5+ec)*8+i)*16+s]=aV[i];
                        }
                    }
                }
                {
                    float aX[8], aL[8];
#pragma unroll
                    for (int i=0;i<8;i++){ aX[i]=0.f; aL[i]=0.f; }
#pragma unroll
                    for (int d=0; d<8; d++){
                        float qbd=qb[d], qtd=qt[d];
                        float4 w0=*(const float4*)(Wb+d*8), w1=*(const float4*)(Wb+d*8+4);
                        float4 x0=*(const float4*)(Xb+d*8), x1=*(const float4*)(Xb+d*8+4);
                        aX[0]=fmaf(qbd,w0.x,aX[0]); aX[1]=fmaf(qbd,w0.y,aX[1]); aX[2]=fmaf(qbd,w0.z,aX[2]); aX[3]=fmaf(qbd,w0.w,aX[3]);
                        aX[4]=fmaf(qbd,w1.x,aX[4]); aX[5]=fmaf(qbd,w1.y,aX[5]); aX[6]=fmaf(qbd,w1.z,aX[6]); aX[7]=fmaf(qbd,w1.w,aX[7]);
                        aL[0]=fmaf(qtd,x0.x,aL[0]); aL[1]=fmaf(qtd,x0.y,aL[1]); aL[2]=fmaf(qtd,x0.z,aL[2]); aL[3]=fmaf(qtd,x0.w,aL[3]);
                        aL[4]=fmaf(qtd,x1.x,aL[4]); aL[5]=fmaf(qtd,x1.y,aL[5]); aL[6]=fmaf(qtd,x1.z,aL[6]); aL[7]=fmaf(qtd,x1.w,aL[7]);
                    }
                    if (!isext){
#pragma unroll
                        for (int i=0;i<8;i++){ prjXT[(pb+i)*16+s]=aX[i]; prjLT[(pb+i)*16+s]=aL[i]; }
                    } else {
#pragma unroll
                        for (int i=0;i<8;i++){
                            extP[((2*5+ec)*8+i)*16+s]=aX[i];
                            extP[((3*5+ec)*8+i)*16+s]=aL[i];
                        }
                    }
                }
            }
        } else {
            int j = tid - 320;
#pragma unroll
            for (int rep=0; rep<2; rep++){
                if (j < 256){
                    int t = j>>4, s = j&15;
                    float acc = 0.f;
#pragma unroll
                    for (int g=0;g<16;g++)
                        acc += dot4v(*(const float4*)&s_k[s*KPAD+4*g], *(const float4*)&s_q[t*KPAD+4*g]);
                    Dsc[j] = acc;
                }
                j += 192;
            }
        }
        __syncthreads();
        {
            int a=tid>>7, i=(tid>>4)&7, s=tid&15;
            float* base = prjULT + a*1408;
            base[(64+i)*16+s] += extP[((a*5+0)*8+i)*16+s];
            base[(72+i)*16+s] += extP[((a*5+1)*8+i)*16+s];
            base[(80+i)*16+s] += extP[((a*5+2)*8+i)*16+s] + extP[((a*5+3)*8+i)*16+s] + extP[((a*5+4)*8+i)*16+s];
        }
        __syncthreads();

        for (int j=tid; j<752; j+=NT){
            if (j < 240){
                int ng = j>>4, t = j&15;
                int pb = s_nd[ng*5+2];
                float4 a0=make_float4(0,0,0,0), a1=a0, a2=a0, a3=a0;
                if (ng < 8){
#pragma unroll
                    for (int i=0;i<4;i++){
                        float w = prjXT[(pb+i)*16+t];
                        const float4* vr = (const float4*)&prjVRT[(pb+i)*16];
                        fma4(a0,w,vr[0]); fma4(a1,w,vr[1]); fma4(a2,w,vr[2]); fma4(a3,w,vr[3]);
                    }
                } else {
#pragma unroll
                    for (int i=0;i<8;i++){
                        float w = prjXT[(pb+i)*16+t];
                        const float4* vr = (const float4*)&prjVRT[(pb+i)*16];
                        fma4(a0,w,vr[0]); fma4(a1,w,vr[1]); fma4(a2,w,vr[2]); fma4(a3,w,vr[3]);
                    }
                }
                int col = ng*16 + t;
                Asc[ 0*240+col]=a0.x;            Asc[ 1*240+col]=(1<=t)?a0.y:0.f;
                Asc[ 2*240+col]=(2<=t)?a0.z:0.f; Asc[ 3*240+col]=(3<=t)?a0.w:0.f;
                Asc[ 4*240+col]=(4<=t)?a1.x:0.f; Asc[ 5*240+col]=(5<=t)?a1.y:0.f;
                Asc[ 6*240+col]=(6<=t)?a1.z:0.f; Asc[ 7*240+col]=(7<=t)?a1.w:0.f;
                Asc[ 8*240+col]=(8<=t)?a2.x:0.f; Asc[ 9*240+col]=(9<=t)?a2.y:0.f;
                Asc[10*240+col]=(10<=t)?a2.z:0.f; Asc[11*240+col]=(11<=t)?a2.w:0.f;
                Asc[12*240+col]=(12<=t)?a3.x:0.f; Asc[13*240+col]=(13<=t)?a3.y:0.f;
                Asc[14*240+col]=(14<=t)?a3.z:0.f; Asc[15*240+col]=(15<=t)?a3.w:0.f;
            } else if (j < 480){
                int jj = j-240;
                int ng = jj>>4, t = jj&15;
                int pb = s_nd[ng*5+2];
                float4 a0=make_float4(0,0,0,0), a1=a0, a2=a0, a3=a0;
                if (ng < 8){
#pragma unroll
                    for (int i=0;i<4;i++){
                        float w = prjLT[(pb+i)*16+t];
                        const float4* ul = (const float4*)&prjULT[(pb+i)*16];
                        fma4(a0,w,ul[0]); fma4(a1,w,ul[1]); fma4(a2,w,ul[2]); fma4(a3,w,ul[3]);
                    }
                } else {
#pragma unroll
                    for (int i=0;i<8;i++){
                        float w = prjLT[(pb+i)*16+t];
                        const float4* ul = (const float4*)&prjULT[(pb+i)*16];
                        fma4(a0,w,ul[0]); fma4(a1,w,ul[1]); fma4(a2,w,ul[2]); fma4(a3,w,ul[3]);
                    }
                }
                int col = ng*16 + t;
                Bsc[ 0*240+col]=a0.x;            Bsc[ 1*240+col]=(1<=t)?a0.y:0.f;
                Bsc[ 2*240+col]=(2<=t)?a0.z:0.f; Bsc[ 3*240+col]=(3<=t)?a0.w:0.f;
                Bsc[ 4*240+col]=(4<=t)?a1.x:0.f; Bsc[ 5*240+col]=(5<=t)?a1.y:0.f;
                Bsc[ 6*240+col]=(6<=t)?a1.z:0.f; Bsc[ 7*240+col]=(7<=t)?a1.w:0.f;
                Bsc[ 8*240+col]=(8<=t)?a2.x:0.f; Bsc[ 9*240+col]=(9<=t)?a2.y:0.f;
                Bsc[10*240+col]=(10<=t)?a2.z:0.f; Bsc[11*240+col]=(11<=t)?a2.w:0.f;
                Bsc[12*240+col]=(12<=t)?a3.x:0.f; Bsc[13*240+col]=(13<=t)?a3.y:0.f;
                Bsc[14*240+col]=(14<=t)?a3.z:0.f; Bsc[15*240+col]=(15<=t)?a3.w:0.f;
            } else if (j < 736){
                int jj = j-480;
                int n = jj>>4, t = jj&15;
                float4 qv = *(const float4*)&s_q[t*KPAD+4*n];
                float cvals[16];
#pragma unroll
                for (int s=0;s<16;s++){
                    float val = dot4v(*(const float4*)&s_v[s*KPAD+4*n], qv);
                    cvals[s] = (s<=t)? val : 0.f;
                }
                float acc0 = dot4v(*(const float4*)&s_leaf[(4*n+0)*4], qv);
                float acc1 = dot4v(*(const float4*)&s_leaf[(4*n+1)*4], qv);
                float acc2 = dot4v(*(const float4*)&s_leaf[(4*n+2)*4], qv);
                float acc3 = dot4v(*(const float4*)&s_leaf[(4*n+3)*4], qv);
#pragma unroll
                for (int s=0;s<16;s++){
                    float4 kv = *(const float4*)&s_k[s*KPAD+4*n];
                    float cs = cvals[s];
                    acc0 = fmaf(kv.x, cs, acc0);
                    acc1 = fmaf(kv.y, cs, acc1);
                    acc2 = fmaf(kv.z, cs, acc2);
                    acc3 = fmaf(kv.w, cs, acc3);
                }
                yl[(4*n+0)*17+t] = acc0;
                yl[(4*n+1)*17+t] = acc1;
                yl[(4*n+2)*17+t] = acc2;
                yl[(4*n+3)*17+t] = acc3;
            } else {
                int t = j-736;
                float acc = 0.f;
#pragma unroll
                for (int g=0;g<16;g++)
                    acc += dot4v(*(const float4*)&s_z[4*g], *(const float4*)&s_q[t*KPAD+4*g]);
                for (int s=0;s<=t;s++) acc += Dsc[t*16+s];
                s_den[t] = fmaxf(acc, 1e-6f);
            }
        }
        __syncthreads();

        for (int j=tid; j<2816; j+=NT){
            if (j < 1408){
                int i88 = j>>4, t = j&15;
                int info = lutP[i88]; int pb = info&255, ng=(info>>8)&255;
                float acc = 0.f;
                int wr = lutWT[i88];
                if (i88 < 32){
#pragma unroll
                    for (int u=0;u<4;u++) acc = fmaf(s_Ws[wr+u], prjXT[(pb+u)*16+t], acc);
                } else {
#pragma unroll
                    for (int u=0;u<8;u++) acc = fmaf(s_Ws[wr+u], prjXT[(pb+u)*16+t], acc);
                }
                const float4* uu4 = (const float4*)&prjULT[i88*16];
                float4 u0=uu4[0], u1=uu4[1], u2=uu4[2], u3=uu4[3];
                const int col = ng*16 + t;
                acc = fmaf(u0.x, Asc[ 0*240+col], acc);
                acc = fmaf(u0.y, Asc[ 1*240+col], acc);
                acc = fmaf(u0.z, Asc[ 2*240+col], acc);
                acc = fmaf(u0.w, Asc[ 3*240+col], acc);
                acc = fmaf(u1.x, Asc[ 4*240+col], acc);
                acc = fmaf(u1.y, Asc[ 5*240+col], acc);
                acc = fmaf(u1.z, Asc[ 6*240+col], acc);
                acc = fmaf(u1.w, Asc[ 7*240+col], acc);
                acc = fmaf(u2.x, Asc[ 8*240+col], acc);
                acc = fmaf(u2.y, Asc[ 9*240+col], acc);
                acc = fmaf(u2.z, Asc[10*240+col], acc);
                acc = fmaf(u2.w, Asc[11*240+col], acc);
                acc = fmaf(u3.x, Asc[12*240+col], acc);
                acc = fmaf(u3.y, Asc[13*240+col], acc);
                acc = fmaf(u3.z, Asc[14*240+col], acc);
                acc = fmaf(u3.w, Asc[15*240+col], acc);
                TT[i88*17+t] = acc;
            } else {
                int jj = j-1408;
                int i88 = jj>>4, t = jj&15;
                int info = lutP[i88]; int pb = info&255, ng=(info>>8)&255;
                float acc = 0.f;
                int wc = lutWB[i88];
                if (i88 < 32){
#pragma unroll
                    for (int u=0;u<4;u++) acc = fmaf(s_Ws[wc+u*4], prjLT[(pb+u)*16+t], acc);
                } else {
#pragma unroll
                    for (int u=0;u<8;u++) acc = fmaf(s_Ws[wc+u*8], prjLT[(pb+u)*16+t], acc);
                }
                const float4* vv4 = (const float4*)&prjVRT[i88*16];
                float4 v0=vv4[0], v1=vv4[1], v2=vv4[2], v3=vv4[3];
                const int col = ng*16 + t;
                acc = fmaf(v0.x, Bsc[ 0*240+col], acc);
                acc = fmaf(v0.y, Bsc[ 1*240+col], acc);
                acc = fmaf(v0.z, Bsc[ 2*240+col], acc);
                acc = fmaf(v0.w, Bsc[ 3*240+col], acc);
                acc = fmaf(v1.x, Bsc[ 4*240+col], acc);
                acc = fmaf(v1.y, Bsc[ 5*240+col], acc);
                acc = fmaf(v1.z, Bsc[ 6*240+col], acc);
                acc = fmaf(v1.w, Bsc[ 7*240+col], acc);
                acc = fmaf(v2.x, Bsc[ 8*240+col], acc);
                acc = fmaf(v2.y, Bsc[ 9*240+col], acc);
                acc = fmaf(v2.z, Bsc[10*240+col], acc);
                acc = fmaf(v2.w, Bsc[11*240+col], acc);
                acc = fmaf(v3.x, Bsc[12*240+col], acc);
                acc = fmaf(v3.y, Bsc[13*240+col], acc);
                acc = fmaf(v3.z, Bsc[14*240+col], acc);
                acc = fmaf(v3.w, Bsc[15*240+col], acc);
                TBB[i88*17+t] = acc;
            }
        }
        __syncthreads();

        for (int j=tid; j<1024; j+=NT){
            int d = j&63, t = j>>6;
            float y = yl[d*17+t];
#pragma unroll
            for (int l=0;l<4;l++){
                const int bs = 4<<l;
                const int r  = (l==0)?4:8;
                const int n = d >> (3+l);
                const int loc = d & (2*bs - 1);
                const int pb = Knro(l) + n*r;
                const int bso = Kbso(l);
                if (loc < bs){
                    const float* u = sUL + bso + loc*r;
#pragma unroll
                    for (int i=0;i<8;i++){
                        if (i < r) y = fmaf(u[i], TT[(pb+i)*17+t], y);
                    }
                } else {
                    const float* u = sUR + bso + (loc-bs)*r;
#pragma unroll
                    for (int i=0;i<8;i++){
                        if (i < r) y = fmaf(u[i], TBB[(pb+i)*17+t], y);
                    }
                }
            }
            float o = y / s_den[t];
            __nv_bfloat16 h = __float2bfloat16(o);
            g_oh[(size_t)t*DH + d] = h;
            g_ol[(size_t)t*DH + d] = __float2bfloat16(o - __bfloat162float(h));
        }
    }
}

// ---------------- output GEMM via mma.sync bf16x3 ----------------
#define WA 72
#define WB 136
#define WO_BYTES ((128*WA*2 + 64*WB*2)*2)
__global__ __launch_bounds__(256) void wo_mma_kernel(float* __restrict__ out){
    extern __shared__ __nv_bfloat16 ws[];
    __nv_bfloat16* sAh = ws;
    __nv_bfloat16* sAl = sAh + 128*WA;
    __nv_bfloat16* sBh = sAl + 128*WA;
    __nv_bfloat16* sBl = sBh + 64*WB;

    const int tid = threadIdx.x;
    const int wid = tid >> 5, lane = tid & 31;
    const int wy = wid & 3, wx = wid >> 2;
    const int rb = blockIdx.x * 128, cb = blockIdx.y * 128;

#pragma unroll
    for (int i=0;i<4;i++){
        int idx = tid + i*256;
        int row = idx >> 3, c8 = idx & 7;
        cp_async16(sAh + row*WA + c8*8, g_ah + (size_t)(rb+row)*DH + c8*8);
        cp_async16(sAl + row*WA + c8*8, g_al + (size_t)(rb+row)*DH + c8*8);
    }
#pragma unroll
    for (int i=0;i<4;i++){
        int idx = tid + i*256;
        int k = idx >> 4, c16 = idx & 15;
        cp_async16(sBh + k*WB + c16*8, g_woh + (size_t)k*DM + cb + c16*8);
        cp_async16(sBl + k*WB + c16*8, g_wol + (size_t)k*DM + cb + c16*8);
    }
    asm volatile("cp.async.commit_group;\n");
    asm volatile("cp.async.wait_group 0;\n");
    __syncthreads();

    float acc[2][8][4];
#pragma unroll
    for (int m=0;m<2;m++)
#pragma unroll
        for (int n=0;n<8;n++){ acc[m][n][0]=acc[m][n][1]=acc[m][n][2]=acc[m][n][3]=0.f; }

#pragma unroll
    for (int k0=0;k0<64;k0+=16){
        unsigned ah[2][4], al[2][4];
#pragma unroll
        for (int mt=0;mt<2;mt++){
            const __nv_bfloat16* ap = sAh + (wy*32 + mt*16 + (lane&15))*WA + k0 + (lane>>4)*8;
            ldmx4(ah[mt][0],ah[mt][1],ah[mt][2],ah[mt][3], ap);
            const __nv_bfloat16* ap2 = sAl + (wy*32 + mt*16 + (lane&15))*WA + k0 + (lane>>4)*8;
            ldmx4(al[mt][0],al[mt][1],al[mt][2],al[mt][3], ap2);
        }
#pragma unroll
        for (int nt=0;nt<4;nt++){
            unsigned bh0,bh1,bh2,bh3, bl0,bl1,bl2,bl3;
            const __nv_bfloat16* bp = sBh + (k0 + (lane&15))*WB + wx*64 + nt*16 + (lane>>4)*8;
            ldmx4t(bh0,bh1,bh2,bh3, bp);
            const __nv_bfloat16* bp2 = sBl + (k0 + (lane&15))*WB + wx*64 + nt*16 + (lane>>4)*8;
            ldmx4t(bl0,bl1,bl2,bl3, bp2);
#pragma unroll
            for (int mt=0;mt<2;mt++){
                mma16816(acc[mt][2*nt],   ah[mt][0],ah[mt][1],ah[mt][2],ah[mt][3], bh0,bh1);
                mma16816(acc[mt][2*nt],   ah[mt][0],ah[mt][1],ah[mt][2],ah[mt][3], bl0,bl1);
                mma16816(acc[mt][2*nt],   al[mt][0],al[mt][1],al[mt][2],al[mt][3], bh0,bh1);
                mma16816(acc[mt][2*nt+1], ah[mt][0],ah[mt][1],ah[mt][2],ah[mt][3], bh2,bh3);
                mma16816(acc[mt][2*nt+1], ah[mt][0],ah[mt][1],ah[mt][2],ah[mt][3], bl2,bl3);
                mma16816(acc[mt][2*nt+1], al[mt][0],al[mt][1],al[mt][2],al[mt][3], bh2,bh3);
            }
        }
    }

#pragma unroll
    for (int mt=0;mt<2;mt++){
        int row = rb + wy*32 + mt*16 + (lane>>2);
#pragma unroll
        for (int nt=0;nt<8;nt++){
            int col = cb + wx*64 + nt*8 + (lane&3)*2;
            *(float2*)(out + (size_t)row*DM + col)     = make_float2(acc[mt][nt][0], acc[mt][nt][1]);
            *(float2*)(out + (size_t)(row+8)*DM + col) = make_float2(acc[mt][nt][2], acc[mt][nt][3]);
        }
    }
}

extern "C" void kernel_launch(void* const* d_in, const int* in_sizes, int n_in,
                              void* d_out, int out_size){
    (void)in_sizes; (void)n_in; (void)out_size;
    const float* x  = (const float*)d_in[0];
    const float* Wq = (const float*)d_in[1];
    const float* Wk = (const float*)d_in[2];
    const float* Wv = (const float*)d_in[3];
    const float* Wo = (const float*)d_in[4];
    BasePtrs bp;
    for(int i=0;i<16;i++) bp.p[i] = (const float*)d_in[5+i];
    float* out = (float*)d_out;

    cudaFuncSetAttribute(chunk_sum4_kernel, cudaFuncAttributeMaxDynamicSharedMemorySize, P1_BYTES);
    cudaFuncSetAttribute(chunk_scan_kernel, cudaFuncAttributeMaxDynamicSharedMemorySize, P3_BYTES);
    cudaFuncSetAttribute(wo_mma_kernel,     cudaFuncAttributeMaxDynamicSharedMemorySize, WO_BYTES);

    wprep_kernel<<<(DM*NW + DH*DM)/256, 256>>>(Wq, Wk, Wv, Wo);
    qkv_mma_kernel<<<NTOK/64, 256>>>(x);
    chunk_sum4_kernel<<<BB*NGRP, NT, P1_BYTES>>>(bp);
    midscan_kernel<<<dim3(NST/128, BB), 128>>>();
    chunk_scan_kernel<<<BB*NCH/2, NT, P3_BYTES>>>(bp);
    wo_mma_kernel<<<dim3(NTOK/128, DM/128), 256, WO_BYTES>>>(out);
}